// round 11
// baseline (speedup 1.0000x reference)
#include <cuda_runtime.h>

// SpanRepLayer, single fused kernel: TT=64 tile, quarter channel split,
// 8 blocks/SM. B=8, K=2048, S=1024, H=256, W=24, WIN=3.

constexpr int Bc = 8;
constexpr int Kc = 2048;
constexpr int Sc = 1024;
constexpr int WINc = 3;

constexpr int TT = 64;          // span-start tile
constexpr int NT = Sc / TT;     // 16 tiles
constexpr int R0 = TT + 23;     // 87 rows (max queried row t0+86)
constexpr int C4 = 16;          // float4 per row (64-channel quarter)
constexpr int LISTCAP = 288;    // mean 128 spans/tile, sd ~11 (+14 sigma)

__device__ __forceinline__ float4 f4max(float4 a, float4 b) {
    return make_float4(fmaxf(a.x, b.x), fmaxf(a.y, b.y),
                       fmaxf(a.z, b.z), fmaxf(a.w, b.w));
}

__global__ __launch_bounds__(256, 8)
void span_fused(const float* __restrict__ tok,
                const int* __restrict__ ids,
                const int* __restrict__ masks,   // bool widened to int32
                float* __restrict__ out)
{
    __shared__ float4 T0[R0 * C4];               // 22272 B
    __shared__ int2 list[LISTCAP];               // (span, ls|le<<8|mask<<16)
    __shared__ int nspan;

    const int tid  = threadIdx.x;
    const int q    = blockIdx.x & 3;             // channel quarter
    const int tile = (blockIdx.x >> 2) & (NT - 1);
    const int b    = blockIdx.x >> 6;
    const int t0   = tile * TT;

    if (tid == 0) nspan = 0;
    __syncthreads();

    // ---- load token slab: rows [t0, t0+87), this block's 64 channels ----
    const float4* g = reinterpret_cast<const float4*>(tok)
                    + (size_t)b * Sc * 64 + q * C4;
    #pragma unroll
    for (int j = 0; j < (R0 * C4 + 255) / 256; j++) {
        const int i = tid + j * 256;
        if (i < R0 * C4) {
            const int r = i >> 4, c = i & 15;
            T0[i] = __ldg(g + (size_t)min(t0 + r, Sc - 1) * 64 + c);
        }
    }

    // ---- scan batch spans (2 per int4 load); compact starts in our tile ----
    const int4* ids4 = reinterpret_cast<const int4*>(ids) + b * (Kc / 2);
    #pragma unroll
    for (int j = 0; j < Kc / 2 / 256; j++) {
        const int idx = tid + j * 256;           // pair index
        const int4 v = __ldg(ids4 + idx);
        if ((v.x >> 6) == tile) {
            const int m = __ldg(masks + b * Kc + 2 * idx) != 0;
            const int p = atomicAdd(&nspan, 1);
            if (p < LISTCAP)
                list[p] = make_int2(b * Kc + 2 * idx,
                                    (v.x - t0) | ((v.y - t0) << 8) | (m << 16));
        }
        if ((v.z >> 6) == tile) {
            const int m = __ldg(masks + b * Kc + 2 * idx + 1) != 0;
            const int p = atomicAdd(&nspan, 1);
            if (p < LISTCAP)
                list[p] = make_int2(b * Kc + 2 * idx + 1,
                                    (v.z - t0) | ((v.w - t0) << 8) | (m << 16));
        }
    }
    __syncthreads();

    // ---- per-half-warp span processing: pure smem + STG ----
    const int wid = tid >> 5, lane = tid & 31;
    const int hw  = lane >> 4, li = lane & 15;   // half-warp id, lane-in-half
    const int n = min(nspan, LISTCAP);
    const float4* Tl = T0 + li;

    for (int i = wid * 2 + hw; i < n; i += 16) { // 8 warps x 2 spans
        const int2 sp = list[i];
        float4* o = reinterpret_cast<float4*>(out)
                  + (size_t)sp.x * 192 + q * C4 + li;

        if ((sp.y & (1 << 16)) == 0) {
            const float4 z = make_float4(0.f, 0.f, 0.f, 0.f);
            o[0] = z; o[64] = z; o[128] = z;
            continue;
        }

        const int ls = sp.y & 0xFF;            // [0,64)
        const int le = (sp.y >> 8) & 0xFF;     // <= 87
        const int w  = le - ls;

        // start: max T0[ls .. ls+min(3,w))
        float4 S = Tl[ls * C4];
        if (w > 1) S = f4max(S, Tl[(ls + 1) * C4]);
        if (w > 2) S = f4max(S, Tl[(ls + 2) * C4]);

        // end: max T0[le-min(3,w) .. le)
        float4 E = Tl[(le - 1) * C4];
        if (w > 1) E = f4max(E, Tl[(le - 2) * C4]);
        if (w > 2) E = f4max(E, Tl[(le - 3) * C4]);

        // inner: rows [ls+3, le-3) when w > 6, else start fallback
        float4 I = S;
        if (w > 2 * WINc) {
            const int a = ls + WINc, e3 = le - WINc;
            float4 I0 = Tl[a * C4];
            float4 I1 = I0;
            int r = a + 1;
            for (; r + 1 < e3; r += 2) {       // 2-way ILP on the chain
                I0 = f4max(I0, Tl[r * C4]);
                I1 = f4max(I1, Tl[(r + 1) * C4]);
            }
            if (r < e3) I0 = f4max(I0, Tl[r * C4]);
            I = f4max(I0, I1);
        }

        o[0] = S; o[64] = I; o[128] = E;
    }
}

extern "C" void kernel_launch(void* const* d_in, const int* in_sizes, int n_in,
                              void* d_out, int out_size)
{
    const float* tok   = (const float*)d_in[0];
    const int*   ids   = (const int*)d_in[1];
    const int*   masks = (const int*)d_in[2];
    float*       out   = (float*)d_out;

    span_fused<<<Bc * NT * 4, 256>>>(tok, ids, masks, out);   // 512 blocks
}

// round 12
// speedup vs baseline: 1.3769x; 1.3769x over previous
#include <cuda_runtime.h>

// SpanRepLayer, single fused kernel. TT=32 tile, half channel split,
// smem slab + smem M3, 2 barriers, scan || M3 build.
// B=8, K=2048, S=1024, H=256, W=24, WIN=3.

constexpr int Bc = 8;
constexpr int Kc = 2048;
constexpr int Sc = 1024;
constexpr int WINc = 3;

constexpr int TT = 32;          // span-start tile
constexpr int NT = Sc / TT;     // 32 tiles
constexpr int R0 = TT + 24;     // 56 rows (max queried row t0+54)
constexpr int R3 = 53;          // M3 rows (max queried idx t0+50)
constexpr int C4 = 32;          // float4 per row (128-channel half)
constexpr int LISTCAP = 192;    // mean 64 spans/tile, sd ~8

__device__ __forceinline__ float4 f4max(float4 a, float4 b) {
    return make_float4(fmaxf(a.x, b.x), fmaxf(a.y, b.y),
                       fmaxf(a.z, b.z), fmaxf(a.w, b.w));
}

__global__ __launch_bounds__(512, 3)
void span_fused(const float* __restrict__ tok,
                const int* __restrict__ ids,
                const int* __restrict__ masks,   // bool widened to int32
                float* __restrict__ out)
{
    __shared__ float4 T0[R0 * C4];               // 28672 B
    __shared__ float4 M3[R3 * C4];               // 27136 B
    __shared__ int2 list[LISTCAP];               // (span, ls|le<<8|mask<<16)
    __shared__ int nspan;

    const int tid  = threadIdx.x;
    const int half = blockIdx.x & 1;             // channel half
    const int tile = (blockIdx.x >> 1) & (NT - 1);
    const int b    = blockIdx.x >> 6;
    const int t0   = tile * TT;

    if (tid == 0) nspan = 0;

    // ---- phase 1: load token slab (rows [t0, t0+56), 128 channels) ----
    const float4* g = reinterpret_cast<const float4*>(tok)
                    + (size_t)b * Sc * 64 + half * C4;
    #pragma unroll
    for (int j = 0; j < (R0 * C4 + 511) / 512; j++) {
        const int i = tid + j * 512;
        if (i < R0 * C4) {
            const int r = i >> 5, c = i & 31;
            T0[i] = __ldg(g + (size_t)min(t0 + r, Sc - 1) * 64 + c);
        }
    }
    __syncthreads();

    // ---- phase 2a: scan batch spans (2 per int4); compact to list ----
    const int4* ids4 = reinterpret_cast<const int4*>(ids) + b * (Kc / 2);
    #pragma unroll
    for (int j = 0; j < Kc / 2 / 512; j++) {
        const int idx = tid + j * 512;           // pair index
        const int4 v = __ldg(ids4 + idx);
        if ((v.x >> 5) == tile) {
            const int m = __ldg(masks + b * Kc + 2 * idx) != 0;
            const int p = atomicAdd(&nspan, 1);
            if (p < LISTCAP)
                list[p] = make_int2(b * Kc + 2 * idx,
                                    (v.x - t0) | ((v.y - t0) << 8) | (m << 16));
        }
        if ((v.z >> 5) == tile) {
            const int m = __ldg(masks + b * Kc + 2 * idx + 1) != 0;
            const int p = atomicAdd(&nspan, 1);
            if (p < LISTCAP)
                list[p] = make_int2(b * Kc + 2 * idx + 1,
                                    (v.z - t0) | ((v.w - t0) << 8) | (m << 16));
        }
    }

    // ---- phase 2b (same phase, overlaps scan): M3[r] = max T0[r..r+2] ----
    #pragma unroll
    for (int j = 0; j < (R3 * C4 + 511) / 512; j++) {
        const int i = tid + j * 512;
        if (i < R3 * C4)
            M3[i] = f4max(f4max(T0[i], T0[i + C4]), T0[i + 2 * C4]);
    }
    __syncthreads();

    // ---- phase 3: per-warp span processing, pure smem + STG ----
    const int wid = tid >> 5, lane = tid & 31;
    const int n = min(nspan, LISTCAP);
    const float4* Tl = T0 + lane;
    const float4* Ml = M3 + lane;

    for (int i = wid; i < n; i += 16) {
        const int2 sp = list[i];
        float4* o = reinterpret_cast<float4*>(out)
                  + (size_t)sp.x * 192 + half * C4 + lane;

        if ((sp.y & (1 << 16)) == 0) {
            const float4 z = make_float4(0.f, 0.f, 0.f, 0.f);
            o[0] = z; o[64] = z; o[128] = z;
            continue;
        }

        const int ls = sp.y & 0xFF;            // [0,32)
        const int le = (sp.y >> 8) & 0xFF;     // <= 55
        const int w  = le - ls;

        float4 S, E;
        if (w >= 3)      { S = Ml[ls * C4]; E = Ml[(le - 3) * C4]; }
        else if (w == 2) { S = f4max(Tl[ls * C4], Tl[(ls + 1) * C4]); E = S; }
        else             { S = Tl[ls * C4]; E = S; }

        // inner [ls+3, le-3), width wp in [1,18] when w>6; else := start
        const int wp = w - 2 * WINc;
        float4 I = S;
        if (wp > 0) {
            const int a = ls + WINc;
            if (wp == 1)      I = Tl[a * C4];
            else if (wp == 2) I = f4max(Tl[a * C4], Tl[(a + 1) * C4]);
            else {
                const int last = a + wp - 3;
                // independent first + last windows, then middle stride-3
                float4 I0 = Ml[a * C4];
                float4 I1 = Ml[last * C4];
                #pragma unroll 4
                for (int p = a + 3; p < last; p += 3)   // <=4 iters
                    I0 = f4max(I0, Ml[p * C4]);
                I = f4max(I0, I1);
            }
        }

        o[0] = S; o[64] = I; o[128] = E;
    }
}

extern "C" void kernel_launch(void* const* d_in, const int* in_sizes, int n_in,
                              void* d_out, int out_size)
{
    const float* tok   = (const float*)d_in[0];
    const int*   ids   = (const int*)d_in[1];
    const int*   masks = (const int*)d_in[2];
    float*       out   = (float*)d_out;

    span_fused<<<Bc * NT * 2, 512>>>(tok, ids, masks, out);   // 512 blocks
}